// round 2
// baseline (speedup 1.0000x reference)
#include <cuda_runtime.h>
#include <cuda_bf16.h>

// Problem: SpikingLayer — inputs = X @ W^T  then LIF scan over T.
// X: [128, 500, 700] fp32, W: [1024, 700] fp32.
// Output: U [128,500,1024] then S [128,500,1024], concatenated in d_out.
//
// Strategy (round 0 baseline):
//   1) fp32 SIMT GEMM (128x128x8 tiles, 8x8/thread) writes inputs into the
//      S half of d_out (reused as scratch).
//   2) scan kernel: 1 thread per (b,h); 8-deep register prefetch ring over t;
//      overwrites the inputs (S region) with spikes in-place (read-ahead by 7
//      guarantees WAR safety within the thread).

static constexpr int M_ = 64000;   // 128 * 500
static constexpr int N_ = 1024;
static constexpr int K_ = 700;
static constexpr int B_ = 128;
static constexpr int T_ = 500;
static constexpr int H_ = 1024;

__device__ __forceinline__ float phi_c()   { return 0.36787944117144233f; } // exp(-1)
__device__ __forceinline__ float gamma_c() { return 0.81873075307798182f; } // exp(-0.2)
__device__ __forceinline__ float beta_c()  { return 0.90483741803595952f; } // exp(-0.1)

// ---------------------------------------------------------------------------
// GEMM: C[m,n] = sum_k A[m,k] * W[n,k]   (both K-major, NT gemm)
// BM=BN=128, BK=8, 256 threads, 8x8 per thread.
// ---------------------------------------------------------------------------
__global__ void __launch_bounds__(256) gemm_nt_kernel(
    const float* __restrict__ A,   // [M_, K_]
    const float* __restrict__ W,   // [N_, K_]
    float* __restrict__ C)         // [M_, N_]
{
    __shared__ float As[8][128];
    __shared__ float Bs[8][128];

    const int tid = threadIdx.x;
    const int bm = blockIdx.y * 128;
    const int bn = blockIdx.x * 128;

    // global-load mapping: 256 threads cover 128 rows x 8 k (float4 each)
    const int lr = tid >> 1;         // 0..127
    const int lk = (tid & 1) * 4;    // 0 or 4
    const float* Aptr = A + (size_t)(bm + lr) * K_ + lk;
    const float* Wptr = W + (size_t)(bn + lr) * K_ + lk;

    // compute mapping: 16x16 threads, 8x8 outputs each
    const int ty = tid >> 4;         // 0..15  -> rows ty*8..ty*8+7
    const int tx = tid & 15;         // 0..15  -> cols tx*8..tx*8+7

    float acc[8][8];
    #pragma unroll
    for (int i = 0; i < 8; i++)
        #pragma unroll
        for (int j = 0; j < 8; j++) acc[i][j] = 0.0f;

    for (int k0 = 0; k0 < K_; k0 += 8) {
        float4 av, bv;
        if (k0 + lk + 4 <= K_) {   // only the tail chunk (k0=696, lk=4) fails
            av = *reinterpret_cast<const float4*>(Aptr + k0);
            bv = *reinterpret_cast<const float4*>(Wptr + k0);
        } else {
            av = make_float4(0.f, 0.f, 0.f, 0.f);
            bv = make_float4(0.f, 0.f, 0.f, 0.f);
        }
        __syncthreads();
        As[lk + 0][lr] = av.x; As[lk + 1][lr] = av.y;
        As[lk + 2][lr] = av.z; As[lk + 3][lr] = av.w;
        Bs[lk + 0][lr] = bv.x; Bs[lk + 1][lr] = bv.y;
        Bs[lk + 2][lr] = bv.z; Bs[lk + 3][lr] = bv.w;
        __syncthreads();

        #pragma unroll
        for (int kk = 0; kk < 8; kk++) {
            float ar[8], br[8];
            *reinterpret_cast<float4*>(&ar[0]) =
                *reinterpret_cast<const float4*>(&As[kk][ty * 8]);
            *reinterpret_cast<float4*>(&ar[4]) =
                *reinterpret_cast<const float4*>(&As[kk][ty * 8 + 4]);
            *reinterpret_cast<float4*>(&br[0]) =
                *reinterpret_cast<const float4*>(&Bs[kk][tx * 8]);
            *reinterpret_cast<float4*>(&br[4]) =
                *reinterpret_cast<const float4*>(&Bs[kk][tx * 8 + 4]);
            #pragma unroll
            for (int i = 0; i < 8; i++)
                #pragma unroll
                for (int j = 0; j < 8; j++)
                    acc[i][j] = fmaf(ar[i], br[j], acc[i][j]);
        }
    }

    // epilogue: M_ % 128 == 0, N_ % 128 == 0 -> no guards
    #pragma unroll
    for (int i = 0; i < 8; i++) {
        float* crow = C + (size_t)(bm + ty * 8 + i) * N_ + bn + tx * 8;
        float4 v0 = make_float4(acc[i][0], acc[i][1], acc[i][2], acc[i][3]);
        float4 v1 = make_float4(acc[i][4], acc[i][5], acc[i][6], acc[i][7]);
        *reinterpret_cast<float4*>(crow)     = v0;
        *reinterpret_cast<float4*>(crow + 4) = v1;
    }
}

// ---------------------------------------------------------------------------
// LIF scan: one thread per (b,h). inputs live in the S region (written by GEMM)
// and are overwritten in-place by the spike output.
// H[t] = PHI*H[t-1] + inp[t-1]
// I[t] = GAMMA*I[t-1] + H[t-1]
// U[t] = BETA*(U[t-1] - I[t-1]) - S[t-1]
// S[t] = (U[t] > 1)
// ---------------------------------------------------------------------------
__global__ void __launch_bounds__(256) lif_scan_kernel(
    float* __restrict__ U,   // [B_, T_, H_]
    float* S)                // [B_, T_, H_]  (holds inputs; NOT restrict: in-place)
{
    const int idx = blockIdx.x * 256 + threadIdx.x;   // 0 .. 131071
    const int b = idx >> 10;
    const int h = idx & 1023;
    const int base = b * (T_ * H_) + h;

    float* Uptr = U + base;
    float* Sptr = S + base;

    // prefetch ring: buf[u] holds inputs at time index (t-1) with (t-1)%8 == u
    float buf[8];
    #pragma unroll
    for (int i = 0; i < 8; i++) buf[i] = Sptr[i * H_];

    Uptr[0] = 0.0f;   // U_REST
    Sptr[0] = 0.0f;

    float Hs = 0.0f, Is = 0.0f, Us = 0.0f, Ss = 0.0f;

    for (int t0 = 1; t0 < T_; t0 += 8) {
        #pragma unroll
        for (int u = 0; u < 8; u++) {
            const int t = t0 + u;
            if (t < T_) {
                const float inp = buf[u];                   // inputs[t-1]
                if (t + 7 < T_) buf[u] = Sptr[(t + 7) * H_]; // prefetch inputs[t+7]
                const float Hn = fmaf(phi_c(), Hs, inp);
                const float In = fmaf(gamma_c(), Is, Hs);
                const float Un = beta_c() * (Us - Is) - Ss;
                const float Sn = (Un > 1.0f) ? 1.0f : 0.0f;
                Uptr[t * H_] = Un;
                Sptr[t * H_] = Sn;
                Hs = Hn; Is = In; Us = Un; Ss = Sn;
            }
        }
    }
}

extern "C" void kernel_launch(void* const* d_in, const int* in_sizes, int n_in,
                              void* d_out, int out_size)
{
    const float* X = (const float*)d_in[0];   // [128, 500, 700]
    const float* W = (const float*)d_in[1];   // [1024, 700]
    float* outU = (float*)d_out;              // [128, 500, 1024]
    float* outS = outU + (size_t)M_ * N_;     // [128, 500, 1024]

    // GEMM writes inputs into the S region (scratch); scan consumes + overwrites.
    dim3 gemm_grid(N_ / 128, M_ / 128);       // (8, 500)
    gemm_nt_kernel<<<gemm_grid, 256>>>(X, W, outS);

    lif_scan_kernel<<<(B_ * H_) / 256, 256>>>(outU, outS);
}